// round 11
// baseline (speedup 1.0000x reference)
#include <cuda_runtime.h>
#include <cuda_bf16.h>

#define NN 100000
#define EE 3200000
#define K_SLOT 80
#define SPILL_MAX 65536

// ---------------- scratch (device globals; no allocations) ----------------
__device__ int   g_esrc2[NN * K_SLOT];   // bucketed src per dst (fixed stride)
__device__ int   g_cnt[NN];
__device__ int   g_spill_s[SPILL_MAX];
__device__ int   g_spill_d[SPILL_MAX];
__device__ int   g_spill_cnt;
__device__ float g_xl1[NN * 16];
__device__ float g_xr1[NN * 16];
__device__ float g_xl2[NN * 8];
__device__ float g_xr2[NN * 8];
__device__ int   g_is64;

// ---------------- helpers ----------------
__device__ __forceinline__ float lrelu02(float x) {
    return fmaxf(x, 0.2f * x);
}

__device__ __forceinline__ void fma2(float2& d, float2 a, float2 b, float2 c) {
    asm("fma.rn.f32x2 %0, %1, %2, %3;"
        : "=l"(reinterpret_cast<unsigned long long&>(d))
        : "l"(reinterpret_cast<unsigned long long&>(a)),
          "l"(reinterpret_cast<unsigned long long&>(b)),
          "l"(reinterpret_cast<unsigned long long&>(c)));
}

// ---------------- K1: zero counters + detect dtype ----------------
__global__ void init_kernel(const long long* __restrict__ ei) {
    int i = blockIdx.x * blockDim.x + threadIdx.x;
    if (i < NN) g_cnt[i] = 0;
    if (blockIdx.x == 0) {
        if (threadIdx.x == 0) g_spill_cnt = 0;
        int bad = 0;
        for (int j = threadIdx.x; j < 2048; j += 1024) {
            long long v = ei[j];
            if (v < 0 || v >= (long long)NN) bad = 1;
        }
        bad = __syncthreads_or(bad);
        if (threadIdx.x == 0) g_is64 = bad ? 0 : 1;
    }
}

// ---------------- K2: single-pass bucket build (2 edges/thread, 16B loads) --
__global__ void build_kernel(const void* __restrict__ ei) {
    int i = (blockIdx.x * blockDim.x + threadIdx.x) * 2;
    if (i >= EE) return;
    int s0, s1, d0, d1;
    if (g_is64) {
        longlong2 sv = *(const longlong2*)((const long long*)ei + i);
        longlong2 dv = *(const longlong2*)((const long long*)ei + EE + i);
        s0 = (int)sv.x; s1 = (int)sv.y;
        d0 = (int)dv.x; d1 = (int)dv.y;
    } else {
        int2 sv = *(const int2*)((const int*)ei + i);
        int2 dv = *(const int2*)((const int*)ei + EE + i);
        s0 = sv.x; s1 = sv.y;
        d0 = dv.x; d1 = dv.y;
    }
    int p0 = atomicAdd(&g_cnt[d0], 1);
    if (p0 < K_SLOT) {
        g_esrc2[d0 * K_SLOT + p0] = s0;
    } else {
        int q = atomicAdd(&g_spill_cnt, 1);
        if (q < SPILL_MAX) { g_spill_s[q] = s0; g_spill_d[q] = d0; }
    }
    int p1 = atomicAdd(&g_cnt[d1], 1);
    if (p1 < K_SLOT) {
        g_esrc2[d1 * K_SLOT + p1] = s1;
    } else {
        int q = atomicAdd(&g_spill_cnt, 1);
        if (q < SPILL_MAX) { g_spill_s[q] = s1; g_spill_d[q] = d1; }
    }
}

// ---------------- K3: GEMM1 — f32x2 packed FMA, 256-node tile, 4 CTAs/SM ----
#define G_NODES 256
#define G_KC    16
#define G_XS    (G_KC + 1)
#define G_SMEM  ((256 * 32 + G_NODES * G_XS) * sizeof(float))

__global__ void __launch_bounds__(256, 4)
gemm1_kernel(const float* __restrict__ x,
             const float* __restrict__ W1l,
             const float* __restrict__ W1r) {
    extern __shared__ float smem[];
    float* Ws = smem;                 // [256 k][32 c]
    float* xs = smem + 256 * 32;      // [256 node][G_XS]

    int t = threadIdx.x;
    for (int i = t; i < 256 * 16; i += 256) {
        int k = i >> 4, c = i & 15;
        Ws[k * 32 + c]      = W1l[i];
        Ws[k * 32 + 16 + c] = W1r[i];
    }

    int nodeBase = blockIdx.x * G_NODES;
    int half = t & 1;            // which 16-col half (0 -> W1l, 1 -> W1r)
    int ng = (t >> 1) * 2;       // node base within tile: 0..254, 2 nodes

    float2 acc[2][8];
#pragma unroll
    for (int m = 0; m < 2; m++)
#pragma unroll
        for (int j = 0; j < 8; j++) acc[m][j] = make_float2(0.f, 0.f);

    for (int kc = 0; kc < 256; kc += G_KC) {
        __syncthreads();
        // 256 nodes x 16 k = 1024 float4; 4 iters.
#pragma unroll
        for (int it = 0; it < 4; it++) {
            int idx = t + 256 * it;
            int node = idx >> 2;
            int k4 = (idx & 3) * 4;
            int gnode = nodeBase + node;
            float4 v = (gnode < NN)
                ? *(const float4*)(x + (size_t)gnode * 256 + kc + k4)
                : make_float4(0.f, 0.f, 0.f, 0.f);
            float* p = xs + node * G_XS + k4;
            p[0] = v.x; p[1] = v.y; p[2] = v.z; p[3] = v.w;
        }
        __syncthreads();

#pragma unroll
        for (int k = 0; k < G_KC; k++) {
            const float4* wp = (const float4*)&Ws[(kc + k) * 32 + half * 16];
            float4 w0 = wp[0], w1 = wp[1], w2 = wp[2], w3 = wp[3];
            float2 w[8];
            w[0] = make_float2(w0.x, w0.y); w[1] = make_float2(w0.z, w0.w);
            w[2] = make_float2(w1.x, w1.y); w[3] = make_float2(w1.z, w1.w);
            w[4] = make_float2(w2.x, w2.y); w[5] = make_float2(w2.z, w2.w);
            w[6] = make_float2(w3.x, w3.y); w[7] = make_float2(w3.z, w3.w);
#pragma unroll
            for (int m = 0; m < 2; m++) {
                float xm = xs[(ng + m) * G_XS + k];
                float2 xp = make_float2(xm, xm);
#pragma unroll
                for (int j = 0; j < 8; j++)
                    fma2(acc[m][j], xp, w[j], acc[m][j]);
            }
        }
    }

    float* base = half ? g_xr1 : g_xl1;
#pragma unroll
    for (int m = 0; m < 2; m++) {
        int node = nodeBase + ng + m;
        if (node < NN) {
            float* dstp = base + node * 16;
            *(float4*)(dstp + 0)  = make_float4(acc[m][0].x, acc[m][0].y, acc[m][1].x, acc[m][1].y);
            *(float4*)(dstp + 4)  = make_float4(acc[m][2].x, acc[m][2].y, acc[m][3].x, acc[m][3].y);
            *(float4*)(dstp + 8)  = make_float4(acc[m][4].x, acc[m][4].y, acc[m][5].x, acc[m][5].y);
            *(float4*)(dstp + 12) = make_float4(acc[m][6].x, acc[m][6].y, acc[m][7].x, acc[m][7].y);
        }
    }
}

// ---------------- K4: edge layer 1 + fused node2 (round-9 winner) ----------
__global__ void __launch_bounds__(128, 14)
edge1_kernel(const float* __restrict__ a1,
             const float* __restrict__ b1,
             const float* __restrict__ W2l,
             const float* __restrict__ W2r) {
    __shared__ float sW[256];   // [k][16]: c<8 -> W2l col c, c>=8 -> W2r col c-8
    int t = threadIdx.x;
    {
        int k = t >> 3, c = t & 7;
        sW[k * 16 + c]     = W2l[t];
        sW[k * 16 + 8 + c] = W2r[t];
    }
    __syncthreads();

    int warp = (blockIdx.x * blockDim.x + t) >> 5;   // grid = exactly NN warps
    int lane = t & 31;
    int h = lane & 3;            // head / float4 index
    int eg = lane >> 2;          // edge slot 0..7

    int d = warp;
    int cnt = g_cnt[d];
    int len = cnt < K_SLOT ? cnt : K_SLOT;
    const int* ep = g_esrc2 + d * K_SLOT;

    float4 aa = __ldg((const float4*)a1 + h);
    float4 xr = *((const float4*)(g_xr1 + d * 16) + h);

    float4 acc = make_float4(0.f, 0.f, 0.f, 0.f);
    float den = 0.0f;
    int lenUp = (len + 7) & ~7;
#pragma unroll 2
    for (int j = eg; j < lenUp; j += 8) {
        bool valid = j < len;
        int s = valid ? ep[j] : 0;
        float4 xl = *((const float4*)(g_xl1 + s * 16) + h);
        float lg = aa.x * lrelu02(xl.x + xr.x)
                 + aa.y * lrelu02(xl.y + xr.y)
                 + aa.z * lrelu02(xl.z + xr.z)
                 + aa.w * lrelu02(xl.w + xr.w);
        float ex = valid ? __expf(lg) : 0.0f;
        den += ex;
        acc.x = fmaf(ex, xl.x, acc.x);
        acc.y = fmaf(ex, xl.y, acc.y);
        acc.z = fmaf(ex, xl.z, acc.z);
        acc.w = fmaf(ex, xl.w, acc.w);
    }
    // spill fallback (empty in practice)
    if (cnt > K_SLOT) {
        int ns = g_spill_cnt; if (ns > SPILL_MAX) ns = SPILL_MAX;
        for (int q = 0; q < ns; q++) {
            if (g_spill_d[q] == d && eg == 0) {
                int s = g_spill_s[q];
                float4 xl = *((const float4*)(g_xl1 + s * 16) + h);
                float lg = aa.x * lrelu02(xl.x + xr.x)
                         + aa.y * lrelu02(xl.y + xr.y)
                         + aa.z * lrelu02(xl.z + xr.z)
                         + aa.w * lrelu02(xl.w + xr.w);
                float ex = __expf(lg);
                den += ex;
                acc.x = fmaf(ex, xl.x, acc.x);
                acc.y = fmaf(ex, xl.y, acc.y);
                acc.z = fmaf(ex, xl.z, acc.z);
                acc.w = fmaf(ex, xl.w, acc.w);
            }
        }
    }
    // reduce across 8 edge groups
#pragma unroll
    for (int o = 4; o < 32; o <<= 1) {
        acc.x += __shfl_xor_sync(0xFFFFFFFFu, acc.x, o);
        acc.y += __shfl_xor_sync(0xFFFFFFFFu, acc.y, o);
        acc.z += __shfl_xor_sync(0xFFFFFFFFu, acc.z, o);
        acc.w += __shfl_xor_sync(0xFFFFFFFFu, acc.w, o);
        den   += __shfl_xor_sync(0xFFFFFFFFu, den, o);
    }

    // fused node2: normalize + bias + ELU (every lane has its head's result)
    float inv = 1.0f / (den + 1e-16f);
    float4 bb = __ldg((const float4*)b1 + h);
    float v4[4];
    {
        float t0 = acc.x * inv + bb.x;
        float t1 = acc.y * inv + bb.y;
        float t2 = acc.z * inv + bb.z;
        float t3 = acc.w * inv + bb.w;
        v4[0] = (t0 > 0.0f) ? t0 : (__expf(t0) - 1.0f);
        v4[1] = (t1 > 0.0f) ? t1 : (__expf(t1) - 1.0f);
        v4[2] = (t2 > 0.0f) ? t2 : (__expf(t2) - 1.0f);
        v4[3] = (t3 > 0.0f) ? t3 : (__expf(t3) - 1.0f);
    }
    // 16-wide transform: v[k] lives in lane (k>>2) (replicated mod 4), reg k&3
    int cc = lane & 15;
    float o = 0.0f;
#pragma unroll
    for (int k = 0; k < 16; k++) {
        float vk = __shfl_sync(0xFFFFFFFFu, v4[k & 3], k >> 2);
        o = fmaf(vk, sW[k * 16 + cc], o);
    }
    if (lane < 8)       g_xl2[d * 8 + lane] = o;
    else if (lane < 16) g_xr2[d * 8 + (lane - 8)] = o;
}

// ---------------- K5: edge layer 2 (round-9 winner) ----------------
__global__ void __launch_bounds__(128, 14)
edge2_kernel(const float* __restrict__ a2,
             const float* __restrict__ b2,
             float* __restrict__ out) {
    int warp = (blockIdx.x * blockDim.x + threadIdx.x) >> 5;
    int lane = threadIdx.x & 31;
    int hf = lane & 1;           // which float4 half of the 8 channels
    int eg = lane >> 1;          // edge slot 0..15

    int d = warp;
    int cnt = g_cnt[d];
    int len = cnt < K_SLOT ? cnt : K_SLOT;
    const int* ep = g_esrc2 + d * K_SLOT;

    float4 aa = __ldg((const float4*)a2 + hf);
    float4 xr = *((const float4*)(g_xr2 + d * 8) + hf);

    float4 acc = make_float4(0.f, 0.f, 0.f, 0.f);
    float den = 0.0f;
    int lenUp = (len + 15) & ~15;
#pragma unroll 2
    for (int j = eg; j < lenUp; j += 16) {
        bool valid = j < len;
        int s = valid ? ep[j] : 0;
        float4 xl = *((const float4*)(g_xl2 + s * 8) + hf);
        float t = aa.x * lrelu02(xl.x + xr.x)
                + aa.y * lrelu02(xl.y + xr.y)
                + aa.z * lrelu02(xl.z + xr.z)
                + aa.w * lrelu02(xl.w + xr.w);
        t += __shfl_xor_sync(0xFFFFFFFFu, t, 1);
        float ex = valid ? __expf(t) : 0.0f;
        den += ex;
        acc.x = fmaf(ex, xl.x, acc.x);
        acc.y = fmaf(ex, xl.y, acc.y);
        acc.z = fmaf(ex, xl.z, acc.z);
        acc.w = fmaf(ex, xl.w, acc.w);
    }
    if (cnt > K_SLOT) {
        int ns = g_spill_cnt; if (ns > SPILL_MAX) ns = SPILL_MAX;
        for (int q = 0; q < ns; q++) {
            if (g_spill_d[q] == d && eg == 0) {
                int s = g_spill_s[q];
                float4 xl = *((const float4*)(g_xl2 + s * 8) + hf);
                float t = aa.x * lrelu02(xl.x + xr.x)
                        + aa.y * lrelu02(xl.y + xr.y)
                        + aa.z * lrelu02(xl.z + xr.z)
                        + aa.w * lrelu02(xl.w + xr.w);
                t += __shfl_xor_sync(0x3u, t, 1);
                float ex = __expf(t);
                den += ex;
                acc.x = fmaf(ex, xl.x, acc.x);
                acc.y = fmaf(ex, xl.y, acc.y);
                acc.z = fmaf(ex, xl.z, acc.z);
                acc.w = fmaf(ex, xl.w, acc.w);
            }
        }
    }
    // reduce across 16 edge groups (keep the lane pair distinct: skip xor 1)
#pragma unroll
    for (int o = 2; o < 32; o <<= 1) {
        acc.x += __shfl_xor_sync(0xFFFFFFFFu, acc.x, o);
        acc.y += __shfl_xor_sync(0xFFFFFFFFu, acc.y, o);
        acc.z += __shfl_xor_sync(0xFFFFFFFFu, acc.z, o);
        acc.w += __shfl_xor_sync(0xFFFFFFFFu, acc.w, o);
        den   += __shfl_xor_sync(0xFFFFFFFFu, den, o);
    }

    if (lane < 2) {   // lane 0: channels 0-3, lane 1: channels 4-7
        float inv = 1.0f / (den + 1e-16f);
        float4 bb = __ldg((const float4*)b2 + lane);
        float4 r;
        r.x = 1.0f / (1.0f + __expf(-(acc.x * inv + bb.x)));
        r.y = 1.0f / (1.0f + __expf(-(acc.y * inv + bb.y)));
        r.z = 1.0f / (1.0f + __expf(-(acc.z * inv + bb.z)));
        r.w = 1.0f / (1.0f + __expf(-(acc.w * inv + bb.w)));
        *((float4*)(out + d * 8) + lane) = r;
    }
}

// ---------------- launch ----------------
extern "C" void kernel_launch(void* const* d_in, const int* in_sizes, int n_in,
                              void* d_out, int out_size) {
    const float* x   = (const float*)d_in[0];
    const void*  ei  = d_in[1];
    const float* W1l = (const float*)d_in[2];
    const float* W1r = (const float*)d_in[3];
    const float* a1  = (const float*)d_in[4];
    const float* b1  = (const float*)d_in[5];
    const float* W2l = (const float*)d_in[6];
    const float* W2r = (const float*)d_in[7];
    const float* a2  = (const float*)d_in[8];
    const float* b2  = (const float*)d_in[9];
    float* out = (float*)d_out;

    static bool configured = false;
    static cudaStream_t s2;
    static cudaEvent_t evA, evB;
    if (!configured) {
        cudaFuncSetAttribute(gemm1_kernel,
                             cudaFuncAttributeMaxDynamicSharedMemorySize,
                             (int)G_SMEM);
        cudaStreamCreateWithFlags(&s2, cudaStreamNonBlocking);
        cudaEventCreateWithFlags(&evA, cudaEventDisableTiming);
        cudaEventCreateWithFlags(&evB, cudaEventDisableTiming);
        configured = true;
    }

    const int NWB = (NN * 32) / 128;   // 25000 blocks of 128 = 100000 warps

    // fork: gemm1 on s2 in parallel with bucket build on default stream
    cudaEventRecord(evA, 0);
    cudaStreamWaitEvent(s2, evA, 0);
    gemm1_kernel<<<(NN + G_NODES - 1) / G_NODES, 256, G_SMEM, s2>>>(x, W1l, W1r);
    cudaEventRecord(evB, s2);

    init_kernel<<<(NN + 1023) / 1024, 1024>>>((const long long*)ei);
    build_kernel<<<(EE / 2 + 255) / 256, 256>>>(ei);

    // join
    cudaStreamWaitEvent(0, evB, 0);
    edge1_kernel<<<NWB, 128>>>(a1, b1, W2l, W2r);
    edge2_kernel<<<NWB, 128>>>(a2, b2, out);
}

// round 13
// speedup vs baseline: 1.0348x; 1.0348x over previous
#include <cuda_runtime.h>
#include <cuda_bf16.h>

#define NN 100000
#define EE 3200000
#define K_SLOT 80
#define SPILL_MAX 65536

// ---------------- scratch (device globals; no allocations) ----------------
__device__ int   g_esrc2[NN * K_SLOT];   // bucketed src per dst (fixed stride)
__device__ int   g_cnt[NN];
__device__ int   g_spill_s[SPILL_MAX];
__device__ int   g_spill_d[SPILL_MAX];
__device__ int   g_spill_cnt;
__device__ float g_xl1[NN * 16];
__device__ float g_xr1[NN * 16];
__device__ float g_xl2[NN * 8];
__device__ float g_xr2[NN * 8];
__device__ int   g_is64;

// ---------------- helpers ----------------
__device__ __forceinline__ float lrelu02(float x) {
    return fmaxf(x, 0.2f * x);
}

__device__ __forceinline__ void fma2(float2& d, float2 a, float2 b, float2 c) {
    asm("fma.rn.f32x2 %0, %1, %2, %3;"
        : "=l"(reinterpret_cast<unsigned long long&>(d))
        : "l"(reinterpret_cast<unsigned long long&>(a)),
          "l"(reinterpret_cast<unsigned long long&>(b)),
          "l"(reinterpret_cast<unsigned long long&>(c)));
}

// 8-byte cp.async: dst needs only 8B alignment (rows are 72B = 8B-aligned).
__device__ __forceinline__ void cpa8(unsigned int dst, const void* src) {
    asm volatile("cp.async.ca.shared.global [%0], [%1], 8;" :: "r"(dst), "l"(src));
}

// ---------------- K1: zero counters + detect dtype ----------------
__global__ void init_kernel(const long long* __restrict__ ei) {
    int i = blockIdx.x * blockDim.x + threadIdx.x;
    if (i < NN) g_cnt[i] = 0;
    if (blockIdx.x == 0) {
        if (threadIdx.x == 0) g_spill_cnt = 0;
        int bad = 0;
        for (int j = threadIdx.x; j < 2048; j += 1024) {
            long long v = ei[j];
            if (v < 0 || v >= (long long)NN) bad = 1;
        }
        bad = __syncthreads_or(bad);
        if (threadIdx.x == 0) g_is64 = bad ? 0 : 1;
    }
}

// ---------------- K2: single-pass bucket build (2 edges/thread, 16B loads) --
__global__ void build_kernel(const void* __restrict__ ei) {
    int i = (blockIdx.x * blockDim.x + threadIdx.x) * 2;
    if (i >= EE) return;
    int s0, s1, d0, d1;
    if (g_is64) {
        longlong2 sv = *(const longlong2*)((const long long*)ei + i);
        longlong2 dv = *(const longlong2*)((const long long*)ei + EE + i);
        s0 = (int)sv.x; s1 = (int)sv.y;
        d0 = (int)dv.x; d1 = (int)dv.y;
    } else {
        int2 sv = *(const int2*)((const int*)ei + i);
        int2 dv = *(const int2*)((const int*)ei + EE + i);
        s0 = sv.x; s1 = sv.y;
        d0 = dv.x; d1 = dv.y;
    }
    int p0 = atomicAdd(&g_cnt[d0], 1);
    if (p0 < K_SLOT) {
        g_esrc2[d0 * K_SLOT + p0] = s0;
    } else {
        int q = atomicAdd(&g_spill_cnt, 1);
        if (q < SPILL_MAX) { g_spill_s[q] = s0; g_spill_d[q] = d0; }
    }
    int p1 = atomicAdd(&g_cnt[d1], 1);
    if (p1 < K_SLOT) {
        g_esrc2[d1 * K_SLOT + p1] = s1;
    } else {
        int q = atomicAdd(&g_spill_cnt, 1);
        if (q < SPILL_MAX) { g_spill_s[q] = s1; g_spill_d[q] = d1; }
    }
}

// ---------------- K3: GEMM1 — f32x2 FMA, 512-tile, cp.async double buffer ---
#define G_NODES 512
#define G_KC    16
#define G_XS    18                      // 72-byte rows: 8B-aligned for cp.async
#define G_XBUF  (G_NODES * G_XS)
#define G_SMEM  ((256 * 32 + 2 * G_XBUF) * sizeof(float))

__global__ void __launch_bounds__(256, 2)
gemm1_kernel(const float* __restrict__ x,
             const float* __restrict__ W1l,
             const float* __restrict__ W1r) {
    extern __shared__ float smem[];
    float* Ws = smem;                 // [256 k][32 c]
    float* xs = smem + 256 * 32;      // [2][512 node][G_XS]

    int t = threadIdx.x;
    for (int i = t; i < 256 * 16; i += 256) {
        int k = i >> 4, c = i & 15;
        Ws[k * 32 + c]      = W1l[i];
        Ws[k * 32 + 16 + c] = W1r[i];
    }

    int nodeBase = blockIdx.x * G_NODES;
    int half = t & 1;
    int ng = (t >> 1) * 4;

    unsigned int xs_u32 = (unsigned int)__cvta_generic_to_shared(xs);

    // issue cp.async for one chunk (16 k-cols of 512 nodes) into buffer `buf`
    // 512 nodes x 16 floats = 4096 8-byte copies / 256 threads = 16 per thread
    auto load_chunk = [&](int kc, int buf) {
        unsigned int base = xs_u32 + buf * (G_XBUF * 4);
#pragma unroll
        for (int it = 0; it < 16; it++) {
            int idx = t + 256 * it;
            int node = idx >> 3;
            int k2 = (idx & 7) * 2;
            int gnode = nodeBase + node;
            unsigned int dst = base + (node * G_XS + k2) * 4;
            if (gnode < NN) {
                cpa8(dst, x + (size_t)gnode * 256 + kc + k2);
            } else {
                asm volatile("st.shared.u64 [%0], %1;"
                             :: "r"(dst), "l"(0ULL) : "memory");
            }
        }
        asm volatile("cp.async.commit_group;" ::: "memory");
    };

    float2 acc[4][8];
#pragma unroll
    for (int m = 0; m < 4; m++)
#pragma unroll
        for (int j = 0; j < 8; j++) acc[m][j] = make_float2(0.f, 0.f);

    load_chunk(0, 0);

    for (int c = 0; c < 16; c++) {
        int kc = c * G_KC;
        if (c + 1 < 16) {
            load_chunk(kc + G_KC, (c + 1) & 1);
            asm volatile("cp.async.wait_group 1;" ::: "memory");
        } else {
            asm volatile("cp.async.wait_group 0;" ::: "memory");
        }
        __syncthreads();

        const float* xb = xs + (c & 1) * G_XBUF;
#pragma unroll
        for (int k = 0; k < G_KC; k++) {
            const float4* wp = (const float4*)&Ws[(kc + k) * 32 + half * 16];
            float4 w0 = wp[0], w1 = wp[1], w2 = wp[2], w3 = wp[3];
            float2 w[8];
            w[0] = make_float2(w0.x, w0.y); w[1] = make_float2(w0.z, w0.w);
            w[2] = make_float2(w1.x, w1.y); w[3] = make_float2(w1.z, w1.w);
            w[4] = make_float2(w2.x, w2.y); w[5] = make_float2(w2.z, w2.w);
            w[6] = make_float2(w3.x, w3.y); w[7] = make_float2(w3.z, w3.w);
#pragma unroll
            for (int m = 0; m < 4; m++) {
                float xm = xb[(ng + m) * G_XS + k];
                float2 xp = make_float2(xm, xm);
#pragma unroll
                for (int j = 0; j < 8; j++)
                    fma2(acc[m][j], xp, w[j], acc[m][j]);
            }
        }
        __syncthreads();
    }

    float* base = half ? g_xr1 : g_xl1;
#pragma unroll
    for (int m = 0; m < 4; m++) {
        int node = nodeBase + ng + m;
        if (node < NN) {
            float* dstp = base + node * 16;
            *(float4*)(dstp + 0)  = make_float4(acc[m][0].x, acc[m][0].y, acc[m][1].x, acc[m][1].y);
            *(float4*)(dstp + 4)  = make_float4(acc[m][2].x, acc[m][2].y, acc[m][3].x, acc[m][3].y);
            *(float4*)(dstp + 8)  = make_float4(acc[m][4].x, acc[m][4].y, acc[m][5].x, acc[m][5].y);
            *(float4*)(dstp + 12) = make_float4(acc[m][6].x, acc[m][6].y, acc[m][7].x, acc[m][7].y);
        }
    }
}

// ---------------- K4: edge layer 1 + fused node2 (round-9 winner) ----------
__global__ void __launch_bounds__(128, 14)
edge1_kernel(const float* __restrict__ a1,
             const float* __restrict__ b1,
             const float* __restrict__ W2l,
             const float* __restrict__ W2r) {
    __shared__ float sW[256];   // [k][16]: c<8 -> W2l col c, c>=8 -> W2r col c-8
    int t = threadIdx.x;
    {
        int k = t >> 3, c = t & 7;
        sW[k * 16 + c]     = W2l[t];
        sW[k * 16 + 8 + c] = W2r[t];
    }
    __syncthreads();

    int warp = (blockIdx.x * blockDim.x + t) >> 5;   // grid = exactly NN warps
    int lane = t & 31;
    int h = lane & 3;            // head / float4 index
    int eg = lane >> 2;          // edge slot 0..7

    int d = warp;
    int cnt = g_cnt[d];
    int len = cnt < K_SLOT ? cnt : K_SLOT;
    const int* ep = g_esrc2 + d * K_SLOT;

    float4 aa = __ldg((const float4*)a1 + h);
    float4 xr = *((const float4*)(g_xr1 + d * 16) + h);

    float4 acc = make_float4(0.f, 0.f, 0.f, 0.f);
    float den = 0.0f;
    int lenUp = (len + 7) & ~7;
#pragma unroll 2
    for (int j = eg; j < lenUp; j += 8) {
        bool valid = j < len;
        int s = valid ? ep[j] : 0;
        float4 xl = *((const float4*)(g_xl1 + s * 16) + h);
        float lg = aa.x * lrelu02(xl.x + xr.x)
                 + aa.y * lrelu02(xl.y + xr.y)
                 + aa.z * lrelu02(xl.z + xr.z)
                 + aa.w * lrelu02(xl.w + xr.w);
        float ex = valid ? __expf(lg) : 0.0f;
        den += ex;
        acc.x = fmaf(ex, xl.x, acc.x);
        acc.y = fmaf(ex, xl.y, acc.y);
        acc.z = fmaf(ex, xl.z, acc.z);
        acc.w = fmaf(ex, xl.w, acc.w);
    }
    // spill fallback (empty in practice)
    if (cnt > K_SLOT) {
        int ns = g_spill_cnt; if (ns > SPILL_MAX) ns = SPILL_MAX;
        for (int q = 0; q < ns; q++) {
            if (g_spill_d[q] == d && eg == 0) {
                int s = g_spill_s[q];
                float4 xl = *((const float4*)(g_xl1 + s * 16) + h);
                float lg = aa.x * lrelu02(xl.x + xr.x)
                         + aa.y * lrelu02(xl.y + xr.y)
                         + aa.z * lrelu02(xl.z + xr.z)
                         + aa.w * lrelu02(xl.w + xr.w);
                float ex = __expf(lg);
                den += ex;
                acc.x = fmaf(ex, xl.x, acc.x);
                acc.y = fmaf(ex, xl.y, acc.y);
                acc.z = fmaf(ex, xl.z, acc.z);
                acc.w = fmaf(ex, xl.w, acc.w);
            }
        }
    }
    // reduce across 8 edge groups
#pragma unroll
    for (int o = 4; o < 32; o <<= 1) {
        acc.x += __shfl_xor_sync(0xFFFFFFFFu, acc.x, o);
        acc.y += __shfl_xor_sync(0xFFFFFFFFu, acc.y, o);
        acc.z += __shfl_xor_sync(0xFFFFFFFFu, acc.z, o);
        acc.w += __shfl_xor_sync(0xFFFFFFFFu, acc.w, o);
        den   += __shfl_xor_sync(0xFFFFFFFFu, den, o);
    }

    // fused node2: normalize + bias + ELU (every lane has its head's result)
    float inv = 1.0f / (den + 1e-16f);
    float4 bb = __ldg((const float4*)b1 + h);
    float v4[4];
    {
        float t0 = acc.x * inv + bb.x;
        float t1 = acc.y * inv + bb.y;
        float t2 = acc.z * inv + bb.z;
        float t3 = acc.w * inv + bb.w;
        v4[0] = (t0 > 0.0f) ? t0 : (__expf(t0) - 1.0f);
        v4[1] = (t1 > 0.0f) ? t1 : (__expf(t1) - 1.0f);
        v4[2] = (t2 > 0.0f) ? t2 : (__expf(t2) - 1.0f);
        v4[3] = (t3 > 0.0f) ? t3 : (__expf(t3) - 1.0f);
    }
    // 16-wide transform: v[k] lives in lane (k>>2) (replicated mod 4), reg k&3
    int cc = lane & 15;
    float o = 0.0f;
#pragma unroll
    for (int k = 0; k < 16; k++) {
        float vk = __shfl_sync(0xFFFFFFFFu, v4[k & 3], k >> 2);
        o = fmaf(vk, sW[k * 16 + cc], o);
    }
    if (lane < 8)       g_xl2[d * 8 + lane] = o;
    else if (lane < 16) g_xr2[d * 8 + (lane - 8)] = o;
}

// ---------------- K5: edge layer 2 (round-9 winner) ----------------
__global__ void __launch_bounds__(128, 14)
edge2_kernel(const float* __restrict__ a2,
             const float* __restrict__ b2,
             float* __restrict__ out) {
    int warp = (blockIdx.x * blockDim.x + threadIdx.x) >> 5;
    int lane = threadIdx.x & 31;
    int hf = lane & 1;           // which float4 half of the 8 channels
    int eg = lane >> 1;          // edge slot 0..15

    int d = warp;
    int cnt = g_cnt[d];
    int len = cnt < K_SLOT ? cnt : K_SLOT;
    const int* ep = g_esrc2 + d * K_SLOT;

    float4 aa = __ldg((const float4*)a2 + hf);
    float4 xr = *((const float4*)(g_xr2 + d * 8) + hf);

    float4 acc = make_float4(0.f, 0.f, 0.f, 0.f);
    float den = 0.0f;
    int lenUp = (len + 15) & ~15;
#pragma unroll 2
    for (int j = eg; j < lenUp; j += 16) {
        bool valid = j < len;
        int s = valid ? ep[j] : 0;
        float4 xl = *((const float4*)(g_xl2 + s * 8) + hf);
        float t = aa.x * lrelu02(xl.x + xr.x)
                + aa.y * lrelu02(xl.y + xr.y)
                + aa.z * lrelu02(xl.z + xr.z)
                + aa.w * lrelu02(xl.w + xr.w);
        t += __shfl_xor_sync(0xFFFFFFFFu, t, 1);
        float ex = valid ? __expf(t) : 0.0f;
        den += ex;
        acc.x = fmaf(ex, xl.x, acc.x);
        acc.y = fmaf(ex, xl.y, acc.y);
        acc.z = fmaf(ex, xl.z, acc.z);
        acc.w = fmaf(ex, xl.w, acc.w);
    }
    if (cnt > K_SLOT) {
        int ns = g_spill_cnt; if (ns > SPILL_MAX) ns = SPILL_MAX;
        for (int q = 0; q < ns; q++) {
            if (g_spill_d[q] == d && eg == 0) {
                int s = g_spill_s[q];
                float4 xl = *((const float4*)(g_xl2 + s * 8) + hf);
                float t = aa.x * lrelu02(xl.x + xr.x)
                        + aa.y * lrelu02(xl.y + xr.y)
                        + aa.z * lrelu02(xl.z + xr.z)
                        + aa.w * lrelu02(xl.w + xr.w);
                t += __shfl_xor_sync(0x3u, t, 1);
                float ex = __expf(t);
                den += ex;
                acc.x = fmaf(ex, xl.x, acc.x);
                acc.y = fmaf(ex, xl.y, acc.y);
                acc.z = fmaf(ex, xl.z, acc.z);
                acc.w = fmaf(ex, xl.w, acc.w);
            }
        }
    }
    // reduce across 16 edge groups (keep the lane pair distinct: skip xor 1)
#pragma unroll
    for (int o = 2; o < 32; o <<= 1) {
        acc.x += __shfl_xor_sync(0xFFFFFFFFu, acc.x, o);
        acc.y += __shfl_xor_sync(0xFFFFFFFFu, acc.y, o);
        acc.z += __shfl_xor_sync(0xFFFFFFFFu, acc.z, o);
        acc.w += __shfl_xor_sync(0xFFFFFFFFu, acc.w, o);
        den   += __shfl_xor_sync(0xFFFFFFFFu, den, o);
    }

    if (lane < 2) {   // lane 0: channels 0-3, lane 1: channels 4-7
        float inv = 1.0f / (den + 1e-16f);
        float4 bb = __ldg((const float4*)b2 + lane);
        float4 r;
        r.x = 1.0f / (1.0f + __expf(-(acc.x * inv + bb.x)));
        r.y = 1.0f / (1.0f + __expf(-(acc.y * inv + bb.y)));
        r.z = 1.0f / (1.0f + __expf(-(acc.z * inv + bb.z)));
        r.w = 1.0f / (1.0f + __expf(-(acc.w * inv + bb.w)));
        *((float4*)(out + d * 8) + lane) = r;
    }
}

// ---------------- launch ----------------
extern "C" void kernel_launch(void* const* d_in, const int* in_sizes, int n_in,
                              void* d_out, int out_size) {
    const float* x   = (const float*)d_in[0];
    const void*  ei  = d_in[1];
    const float* W1l = (const float*)d_in[2];
    const float* W1r = (const float*)d_in[3];
    const float* a1  = (const float*)d_in[4];
    const float* b1  = (const float*)d_in[5];
    const float* W2l = (const float*)d_in[6];
    const float* W2r = (const float*)d_in[7];
    const float* a2  = (const float*)d_in[8];
    const float* b2  = (const float*)d_in[9];
    float* out = (float*)d_out;

    static bool configured = false;
    static cudaStream_t s2;
    static cudaEvent_t evA, evB;
    if (!configured) {
        cudaFuncSetAttribute(gemm1_kernel,
                             cudaFuncAttributeMaxDynamicSharedMemorySize,
                             (int)G_SMEM);
        cudaStreamCreateWithFlags(&s2, cudaStreamNonBlocking);
        cudaEventCreateWithFlags(&evA, cudaEventDisableTiming);
        cudaEventCreateWithFlags(&evB, cudaEventDisableTiming);
        configured = true;
    }

    const int NWB = (NN * 32) / 128;   // 25000 blocks of 128 = 100000 warps

    // fork: gemm1 on s2 in parallel with bucket build on default stream
    cudaEventRecord(evA, 0);
    cudaStreamWaitEvent(s2, evA, 0);
    gemm1_kernel<<<(NN + G_NODES - 1) / G_NODES, 256, G_SMEM, s2>>>(x, W1l, W1r);
    cudaEventRecord(evB, s2);

    init_kernel<<<(NN + 1023) / 1024, 1024>>>((const long long*)ei);
    build_kernel<<<(EE / 2 + 255) / 256, 256>>>(ei);

    // join
    cudaStreamWaitEvent(0, evB, 0);
    edge1_kernel<<<NWB, 128>>>(a1, b1, W2l, W2r);
    edge2_kernel<<<NWB, 128>>>(a2, b2, out);
}

// round 14
// speedup vs baseline: 1.1721x; 1.1327x over previous
#include <cuda_runtime.h>
#include <cuda_bf16.h>

#define NN 100000
#define EE 3200000
#define K_SLOT 80
#define SPILL_MAX 65536

// ---------------- scratch (device globals; no allocations) ----------------
__device__ int   g_esrc2[NN * K_SLOT];   // bucketed src per dst (fixed stride)
__device__ int   g_cnt[NN];
__device__ int   g_spill_s[SPILL_MAX];
__device__ int   g_spill_d[SPILL_MAX];
__device__ int   g_spill_cnt;
__device__ float g_xl1[NN * 16];
__device__ float g_xr1[NN * 16];
__device__ float g_xl2[NN * 8];
__device__ float g_xr2[NN * 8];
__device__ int   g_is64;

// ---------------- helpers ----------------
__device__ __forceinline__ float lrelu02(float x) {
    return fmaxf(x, 0.2f * x);
}

__device__ __forceinline__ void fma2(float2& d, float2 a, float2 b, float2 c) {
    asm("fma.rn.f32x2 %0, %1, %2, %3;"
        : "=l"(reinterpret_cast<unsigned long long&>(d))
        : "l"(reinterpret_cast<unsigned long long&>(a)),
          "l"(reinterpret_cast<unsigned long long&>(b)),
          "l"(reinterpret_cast<unsigned long long&>(c)));
}

// ---------------- K1: zero counters + detect dtype ----------------
__global__ void init_kernel(const long long* __restrict__ ei) {
    int i = blockIdx.x * blockDim.x + threadIdx.x;
    if (i < NN) g_cnt[i] = 0;
    if (blockIdx.x == 0) {
        if (threadIdx.x == 0) g_spill_cnt = 0;
        int bad = 0;
        for (int j = threadIdx.x; j < 2048; j += 1024) {
            long long v = ei[j];
            if (v < 0 || v >= (long long)NN) bad = 1;
        }
        bad = __syncthreads_or(bad);
        if (threadIdx.x == 0) g_is64 = bad ? 0 : 1;
    }
}

// ---------------- K2: single-pass bucket build (2 edges/thread, 16B loads) --
__global__ void build_kernel(const void* __restrict__ ei) {
    int i = (blockIdx.x * blockDim.x + threadIdx.x) * 2;
    if (i >= EE) return;
    int s0, s1, d0, d1;
    if (g_is64) {
        longlong2 sv = *(const longlong2*)((const long long*)ei + i);
        longlong2 dv = *(const longlong2*)((const long long*)ei + EE + i);
        s0 = (int)sv.x; s1 = (int)sv.y;
        d0 = (int)dv.x; d1 = (int)dv.y;
    } else {
        int2 sv = *(const int2*)((const int*)ei + i);
        int2 dv = *(const int2*)((const int*)ei + EE + i);
        s0 = sv.x; s1 = sv.y;
        d0 = dv.x; d1 = dv.y;
    }
    int p0 = atomicAdd(&g_cnt[d0], 1);
    if (p0 < K_SLOT) {
        g_esrc2[d0 * K_SLOT + p0] = s0;
    } else {
        int q = atomicAdd(&g_spill_cnt, 1);
        if (q < SPILL_MAX) { g_spill_s[q] = s0; g_spill_d[q] = d0; }
    }
    int p1 = atomicAdd(&g_cnt[d1], 1);
    if (p1 < K_SLOT) {
        g_esrc2[d1 * K_SLOT + p1] = s1;
    } else {
        int q = atomicAdd(&g_spill_cnt, 1);
        if (q < SPILL_MAX) { g_spill_s[q] = s1; g_spill_d[q] = d1; }
    }
}

// ---------------- K3: GEMM1 — f32x2 FMA, 384-node tile, 3 CTAs/SM ----------
// grid = 261 -> worst SM runs 2 CTAs of 0.75 units (vs 512-tile's 2 x 1.0).
#define G_NODES 384
#define G_KC    16
#define G_XS    (G_KC + 1)
#define G_SMEM  ((256 * 32 + G_NODES * G_XS) * sizeof(float))

__global__ void __launch_bounds__(256, 3)
gemm1_kernel(const float* __restrict__ x,
             const float* __restrict__ W1l,
             const float* __restrict__ W1r) {
    extern __shared__ float smem[];
    float* Ws = smem;                 // [256 k][32 c]
    float* xs = smem + 256 * 32;      // [384 node][G_XS]

    int t = threadIdx.x;
    for (int i = t; i < 256 * 16; i += 256) {
        int k = i >> 4, c = i & 15;
        Ws[k * 32 + c]      = W1l[i];
        Ws[k * 32 + 16 + c] = W1r[i];
    }

    int nodeBase = blockIdx.x * G_NODES;
    int half = t & 1;            // which 16-col half (0 -> W1l, 1 -> W1r)
    int ng = (t >> 1) * 3;       // node base within tile: 0..381

    float2 acc[3][8];
#pragma unroll
    for (int m = 0; m < 3; m++)
#pragma unroll
        for (int j = 0; j < 8; j++) acc[m][j] = make_float2(0.f, 0.f);

    for (int kc = 0; kc < 256; kc += G_KC) {
        __syncthreads();
        // 384 nodes x 16 k = 1536 float4; 6 iters.
#pragma unroll
        for (int it = 0; it < 6; it++) {
            int idx = t + 256 * it;
            int node = idx >> 2;
            int k4 = (idx & 3) * 4;
            int gnode = nodeBase + node;
            float4 v = (gnode < NN)
                ? *(const float4*)(x + (size_t)gnode * 256 + kc + k4)
                : make_float4(0.f, 0.f, 0.f, 0.f);
            float* p = xs + node * G_XS + k4;
            p[0] = v.x; p[1] = v.y; p[2] = v.z; p[3] = v.w;
        }
        __syncthreads();

#pragma unroll
        for (int k = 0; k < G_KC; k++) {
            const float4* wp = (const float4*)&Ws[(kc + k) * 32 + half * 16];
            float4 w0 = wp[0], w1 = wp[1], w2 = wp[2], w3 = wp[3];
            float2 w[8];
            w[0] = make_float2(w0.x, w0.y); w[1] = make_float2(w0.z, w0.w);
            w[2] = make_float2(w1.x, w1.y); w[3] = make_float2(w1.z, w1.w);
            w[4] = make_float2(w2.x, w2.y); w[5] = make_float2(w2.z, w2.w);
            w[6] = make_float2(w3.x, w3.y); w[7] = make_float2(w3.z, w3.w);
#pragma unroll
            for (int m = 0; m < 3; m++) {
                float xm = xs[(ng + m) * G_XS + k];
                float2 xp = make_float2(xm, xm);
#pragma unroll
                for (int j = 0; j < 8; j++)
                    fma2(acc[m][j], xp, w[j], acc[m][j]);
            }
        }
    }

    float* base = half ? g_xr1 : g_xl1;
#pragma unroll
    for (int m = 0; m < 3; m++) {
        int node = nodeBase + ng + m;
        if (node < NN) {
            float* dstp = base + node * 16;
            *(float4*)(dstp + 0)  = make_float4(acc[m][0].x, acc[m][0].y, acc[m][1].x, acc[m][1].y);
            *(float4*)(dstp + 4)  = make_float4(acc[m][2].x, acc[m][2].y, acc[m][3].x, acc[m][3].y);
            *(float4*)(dstp + 8)  = make_float4(acc[m][4].x, acc[m][4].y, acc[m][5].x, acc[m][5].y);
            *(float4*)(dstp + 12) = make_float4(acc[m][6].x, acc[m][6].y, acc[m][7].x, acc[m][7].y);
        }
    }
}

// ---------------- K4: edge layer 1 + fused node2 (round-9 winner) ----------
__global__ void __launch_bounds__(128, 14)
edge1_kernel(const float* __restrict__ a1,
             const float* __restrict__ b1,
             const float* __restrict__ W2l,
             const float* __restrict__ W2r) {
    __shared__ float sW[256];   // [k][16]: c<8 -> W2l col c, c>=8 -> W2r col c-8
    int t = threadIdx.x;
    {
        int k = t >> 3, c = t & 7;
        sW[k * 16 + c]     = W2l[t];
        sW[k * 16 + 8 + c] = W2r[t];
    }
    __syncthreads();

    int warp = (blockIdx.x * blockDim.x + t) >> 5;   // grid = exactly NN warps
    int lane = t & 31;
    int h = lane & 3;            // head / float4 index
    int eg = lane >> 2;          // edge slot 0..7

    int d = warp;
    int cnt = g_cnt[d];
    int len = cnt < K_SLOT ? cnt : K_SLOT;
    const int* ep = g_esrc2 + d * K_SLOT;

    float4 aa = __ldg((const float4*)a1 + h);
    float4 xr = *((const float4*)(g_xr1 + d * 16) + h);

    float4 acc = make_float4(0.f, 0.f, 0.f, 0.f);
    float den = 0.0f;
    int lenUp = (len + 7) & ~7;
#pragma unroll 2
    for (int j = eg; j < lenUp; j += 8) {
        bool valid = j < len;
        int s = valid ? ep[j] : 0;
        float4 xl = *((const float4*)(g_xl1 + s * 16) + h);
        float lg = aa.x * lrelu02(xl.x + xr.x)
                 + aa.y * lrelu02(xl.y + xr.y)
                 + aa.z * lrelu02(xl.z + xr.z)
                 + aa.w * lrelu02(xl.w + xr.w);
        float ex = valid ? __expf(lg) : 0.0f;
        den += ex;
        acc.x = fmaf(ex, xl.x, acc.x);
        acc.y = fmaf(ex, xl.y, acc.y);
        acc.z = fmaf(ex, xl.z, acc.z);
        acc.w = fmaf(ex, xl.w, acc.w);
    }
    // spill fallback (empty in practice)
    if (cnt > K_SLOT) {
        int ns = g_spill_cnt; if (ns > SPILL_MAX) ns = SPILL_MAX;
        for (int q = 0; q < ns; q++) {
            if (g_spill_d[q] == d && eg == 0) {
                int s = g_spill_s[q];
                float4 xl = *((const float4*)(g_xl1 + s * 16) + h);
                float lg = aa.x * lrelu02(xl.x + xr.x)
                         + aa.y * lrelu02(xl.y + xr.y)
                         + aa.z * lrelu02(xl.z + xr.z)
                         + aa.w * lrelu02(xl.w + xr.w);
                float ex = __expf(lg);
                den += ex;
                acc.x = fmaf(ex, xl.x, acc.x);
                acc.y = fmaf(ex, xl.y, acc.y);
                acc.z = fmaf(ex, xl.z, acc.z);
                acc.w = fmaf(ex, xl.w, acc.w);
            }
        }
    }
    // reduce across 8 edge groups
#pragma unroll
    for (int o = 4; o < 32; o <<= 1) {
        acc.x += __shfl_xor_sync(0xFFFFFFFFu, acc.x, o);
        acc.y += __shfl_xor_sync(0xFFFFFFFFu, acc.y, o);
        acc.z += __shfl_xor_sync(0xFFFFFFFFu, acc.z, o);
        acc.w += __shfl_xor_sync(0xFFFFFFFFu, acc.w, o);
        den   += __shfl_xor_sync(0xFFFFFFFFu, den, o);
    }

    // fused node2: normalize + bias + ELU (every lane has its head's result)
    float inv = 1.0f / (den + 1e-16f);
    float4 bb = __ldg((const float4*)b1 + h);
    float v4[4];
    {
        float t0 = acc.x * inv + bb.x;
        float t1 = acc.y * inv + bb.y;
        float t2 = acc.z * inv + bb.z;
        float t3 = acc.w * inv + bb.w;
        v4[0] = (t0 > 0.0f) ? t0 : (__expf(t0) - 1.0f);
        v4[1] = (t1 > 0.0f) ? t1 : (__expf(t1) - 1.0f);
        v4[2] = (t2 > 0.0f) ? t2 : (__expf(t2) - 1.0f);
        v4[3] = (t3 > 0.0f) ? t3 : (__expf(t3) - 1.0f);
    }
    // 16-wide transform: v[k] lives in lane (k>>2) (replicated mod 4), reg k&3
    int cc = lane & 15;
    float o = 0.0f;
#pragma unroll
    for (int k = 0; k < 16; k++) {
        float vk = __shfl_sync(0xFFFFFFFFu, v4[k & 3], k >> 2);
        o = fmaf(vk, sW[k * 16 + cc], o);
    }
    if (lane < 8)       g_xl2[d * 8 + lane] = o;
    else if (lane < 16) g_xr2[d * 8 + (lane - 8)] = o;
}

// ---------------- K5: edge layer 2 (round-9 winner) ----------------
__global__ void __launch_bounds__(128, 14)
edge2_kernel(const float* __restrict__ a2,
             const float* __restrict__ b2,
             float* __restrict__ out) {
    int warp = (blockIdx.x * blockDim.x + threadIdx.x) >> 5;
    int lane = threadIdx.x & 31;
    int hf = lane & 1;           // which float4 half of the 8 channels
    int eg = lane >> 1;          // edge slot 0..15

    int d = warp;
    int cnt = g_cnt[d];
    int len = cnt < K_SLOT ? cnt : K_SLOT;
    const int* ep = g_esrc2 + d * K_SLOT;

    float4 aa = __ldg((const float4*)a2 + hf);
    float4 xr = *((const float4*)(g_xr2 + d * 8) + hf);

    float4 acc = make_float4(0.f, 0.f, 0.f, 0.f);
    float den = 0.0f;
    int lenUp = (len + 15) & ~15;
#pragma unroll 2
    for (int j = eg; j < lenUp; j += 16) {
        bool valid = j < len;
        int s = valid ? ep[j] : 0;
        float4 xl = *((const float4*)(g_xl2 + s * 8) + hf);
        float t = aa.x * lrelu02(xl.x + xr.x)
                + aa.y * lrelu02(xl.y + xr.y)
                + aa.z * lrelu02(xl.z + xr.z)
                + aa.w * lrelu02(xl.w + xr.w);
        t += __shfl_xor_sync(0xFFFFFFFFu, t, 1);
        float ex = valid ? __expf(t) : 0.0f;
        den += ex;
        acc.x = fmaf(ex, xl.x, acc.x);
        acc.y = fmaf(ex, xl.y, acc.y);
        acc.z = fmaf(ex, xl.z, acc.z);
        acc.w = fmaf(ex, xl.w, acc.w);
    }
    if (cnt > K_SLOT) {
        int ns = g_spill_cnt; if (ns > SPILL_MAX) ns = SPILL_MAX;
        for (int q = 0; q < ns; q++) {
            if (g_spill_d[q] == d && eg == 0) {
                int s = g_spill_s[q];
                float4 xl = *((const float4*)(g_xl2 + s * 8) + hf);
                float t = aa.x * lrelu02(xl.x + xr.x)
                        + aa.y * lrelu02(xl.y + xr.y)
                        + aa.z * lrelu02(xl.z + xr.z)
                        + aa.w * lrelu02(xl.w + xr.w);
                t += __shfl_xor_sync(0x3u, t, 1);
                float ex = __expf(t);
                den += ex;
                acc.x = fmaf(ex, xl.x, acc.x);
                acc.y = fmaf(ex, xl.y, acc.y);
                acc.z = fmaf(ex, xl.z, acc.z);
                acc.w = fmaf(ex, xl.w, acc.w);
            }
        }
    }
    // reduce across 16 edge groups (keep the lane pair distinct: skip xor 1)
#pragma unroll
    for (int o = 2; o < 32; o <<= 1) {
        acc.x += __shfl_xor_sync(0xFFFFFFFFu, acc.x, o);
        acc.y += __shfl_xor_sync(0xFFFFFFFFu, acc.y, o);
        acc.z += __shfl_xor_sync(0xFFFFFFFFu, acc.z, o);
        acc.w += __shfl_xor_sync(0xFFFFFFFFu, acc.w, o);
        den   += __shfl_xor_sync(0xFFFFFFFFu, den, o);
    }

    if (lane < 2) {   // lane 0: channels 0-3, lane 1: channels 4-7
        float inv = 1.0f / (den + 1e-16f);
        float4 bb = __ldg((const float4*)b2 + lane);
        float4 r;
        r.x = 1.0f / (1.0f + __expf(-(acc.x * inv + bb.x)));
        r.y = 1.0f / (1.0f + __expf(-(acc.y * inv + bb.y)));
        r.z = 1.0f / (1.0f + __expf(-(acc.z * inv + bb.z)));
        r.w = 1.0f / (1.0f + __expf(-(acc.w * inv + bb.w)));
        *((float4*)(out + d * 8) + lane) = r;
    }
}

// ---------------- launch ----------------
extern "C" void kernel_launch(void* const* d_in, const int* in_sizes, int n_in,
                              void* d_out, int out_size) {
    const float* x   = (const float*)d_in[0];
    const void*  ei  = d_in[1];
    const float* W1l = (const float*)d_in[2];
    const float* W1r = (const float*)d_in[3];
    const float* a1  = (const float*)d_in[4];
    const float* b1  = (const float*)d_in[5];
    const float* W2l = (const float*)d_in[6];
    const float* W2r = (const float*)d_in[7];
    const float* a2  = (const float*)d_in[8];
    const float* b2  = (const float*)d_in[9];
    float* out = (float*)d_out;

    static bool configured = false;
    static cudaStream_t s2;
    static cudaEvent_t evA, evB;
    if (!configured) {
        cudaFuncSetAttribute(gemm1_kernel,
                             cudaFuncAttributeMaxDynamicSharedMemorySize,
                             (int)G_SMEM);
        cudaStreamCreateWithFlags(&s2, cudaStreamNonBlocking);
        cudaEventCreateWithFlags(&evA, cudaEventDisableTiming);
        cudaEventCreateWithFlags(&evB, cudaEventDisableTiming);
        configured = true;
    }

    const int NWB = (NN * 32) / 128;   // 25000 blocks of 128 = 100000 warps

    // fork: gemm1 on s2 in parallel with bucket build on default stream
    cudaEventRecord(evA, 0);
    cudaStreamWaitEvent(s2, evA, 0);
    gemm1_kernel<<<(NN + G_NODES - 1) / G_NODES, 256, G_SMEM, s2>>>(x, W1l, W1r);
    cudaEventRecord(evB, s2);

    init_kernel<<<(NN + 1023) / 1024, 1024>>>((const long long*)ei);
    build_kernel<<<(EE / 2 + 255) / 256, 256>>>(ei);

    // join
    cudaStreamWaitEvent(0, evB, 0);
    edge1_kernel<<<NWB, 128>>>(a1, b1, W2l, W2r);
    edge2_kernel<<<NWB, 128>>>(a2, b2, out);
}

// round 15
// speedup vs baseline: 1.1892x; 1.0146x over previous
#include <cuda_runtime.h>
#include <cuda_bf16.h>

#define NN 100000
#define EE 3200000
#define K_SLOT 80
#define SPILL_MAX 65536

// ---------------- scratch (device globals; no allocations) ----------------
__device__ int   g_esrc2[NN * K_SLOT];   // bucketed src per dst (fixed stride)
__device__ int   g_cnt[NN];
__device__ int   g_spill_s[SPILL_MAX];
__device__ int   g_spill_d[SPILL_MAX];
__device__ int   g_spill_cnt;
__device__ float g_xl1[NN * 16];
__device__ float g_xr1[NN * 16];
__device__ float g_xl2[NN * 8];
__device__ float g_xr2[NN * 8];
__device__ int   g_is64;

// ---------------- helpers ----------------
__device__ __forceinline__ float lrelu02(float x) {
    return fmaxf(x, 0.2f * x);
}

__device__ __forceinline__ void fma2(float2& d, float2 a, float2 b, float2 c) {
    asm("fma.rn.f32x2 %0, %1, %2, %3;"
        : "=l"(reinterpret_cast<unsigned long long&>(d))
        : "l"(reinterpret_cast<unsigned long long&>(a)),
          "l"(reinterpret_cast<unsigned long long&>(b)),
          "l"(reinterpret_cast<unsigned long long&>(c)));
}

__device__ __forceinline__ float2 add2(float2 a, float2 b) {
    float2 d;
    asm("add.rn.f32x2 %0, %1, %2;"
        : "=l"(reinterpret_cast<unsigned long long&>(d))
        : "l"(reinterpret_cast<unsigned long long&>(a)),
          "l"(reinterpret_cast<unsigned long long&>(b)));
    return d;
}

__device__ __forceinline__ float2 mul2(float2 a, float2 b) {
    float2 d;
    asm("mul.rn.f32x2 %0, %1, %2;"
        : "=l"(reinterpret_cast<unsigned long long&>(d))
        : "l"(reinterpret_cast<unsigned long long&>(a)),
          "l"(reinterpret_cast<unsigned long long&>(b)));
    return d;
}

// ---------------- K1: zero counters + detect dtype ----------------
__global__ void init_kernel(const long long* __restrict__ ei) {
    int i = blockIdx.x * blockDim.x + threadIdx.x;
    if (i < NN) g_cnt[i] = 0;
    if (blockIdx.x == 0) {
        if (threadIdx.x == 0) g_spill_cnt = 0;
        int bad = 0;
        for (int j = threadIdx.x; j < 2048; j += 1024) {
            long long v = ei[j];
            if (v < 0 || v >= (long long)NN) bad = 1;
        }
        bad = __syncthreads_or(bad);
        if (threadIdx.x == 0) g_is64 = bad ? 0 : 1;
    }
}

// ---------------- K2: single-pass bucket build (2 edges/thread, 16B loads) --
__global__ void build_kernel(const void* __restrict__ ei) {
    int i = (blockIdx.x * blockDim.x + threadIdx.x) * 2;
    if (i >= EE) return;
    int s0, s1, d0, d1;
    if (g_is64) {
        longlong2 sv = *(const longlong2*)((const long long*)ei + i);
        longlong2 dv = *(const longlong2*)((const long long*)ei + EE + i);
        s0 = (int)sv.x; s1 = (int)sv.y;
        d0 = (int)dv.x; d1 = (int)dv.y;
    } else {
        int2 sv = *(const int2*)((const int*)ei + i);
        int2 dv = *(const int2*)((const int*)ei + EE + i);
        s0 = sv.x; s1 = sv.y;
        d0 = dv.x; d1 = dv.y;
    }
    int p0 = atomicAdd(&g_cnt[d0], 1);
    if (p0 < K_SLOT) {
        g_esrc2[d0 * K_SLOT + p0] = s0;
    } else {
        int q = atomicAdd(&g_spill_cnt, 1);
        if (q < SPILL_MAX) { g_spill_s[q] = s0; g_spill_d[q] = d0; }
    }
    int p1 = atomicAdd(&g_cnt[d1], 1);
    if (p1 < K_SLOT) {
        g_esrc2[d1 * K_SLOT + p1] = s1;
    } else {
        int q = atomicAdd(&g_spill_cnt, 1);
        if (q < SPILL_MAX) { g_spill_s[q] = s1; g_spill_d[q] = d1; }
    }
}

// ---------------- K3: GEMM1 — f32x2 packed FMA (round-9 winner) ------------
#define G_NODES 512
#define G_KC    16
#define G_XS    (G_KC + 1)
#define G_SMEM  ((256 * 32 + G_NODES * G_XS) * sizeof(float))

__global__ void __launch_bounds__(256, 2)
gemm1_kernel(const float* __restrict__ x,
             const float* __restrict__ W1l,
             const float* __restrict__ W1r) {
    extern __shared__ float smem[];
    float* Ws = smem;                 // [256 k][32 c]
    float* xs = smem + 256 * 32;      // [512 node][G_XS]

    int t = threadIdx.x;
    for (int i = t; i < 256 * 16; i += 256) {
        int k = i >> 4, c = i & 15;
        Ws[k * 32 + c]      = W1l[i];
        Ws[k * 32 + 16 + c] = W1r[i];
    }

    int nodeBase = blockIdx.x * G_NODES;
    int half = t & 1;
    int ng = (t >> 1) * 4;

    float2 acc[4][8];
#pragma unroll
    for (int m = 0; m < 4; m++)
#pragma unroll
        for (int j = 0; j < 8; j++) acc[m][j] = make_float2(0.f, 0.f);

    for (int kc = 0; kc < 256; kc += G_KC) {
        __syncthreads();
#pragma unroll
        for (int it = 0; it < 8; it++) {
            int idx = t + 256 * it;
            int node = idx >> 2;
            int k4 = (idx & 3) * 4;
            int gnode = nodeBase + node;
            float4 v = (gnode < NN)
                ? *(const float4*)(x + (size_t)gnode * 256 + kc + k4)
                : make_float4(0.f, 0.f, 0.f, 0.f);
            float* p = xs + node * G_XS + k4;
            p[0] = v.x; p[1] = v.y; p[2] = v.z; p[3] = v.w;
        }
        __syncthreads();

#pragma unroll
        for (int k = 0; k < G_KC; k++) {
            const float4* wp = (const float4*)&Ws[(kc + k) * 32 + half * 16];
            float4 w0 = wp[0], w1 = wp[1], w2 = wp[2], w3 = wp[3];
            float2 w[8];
            w[0] = make_float2(w0.x, w0.y); w[1] = make_float2(w0.z, w0.w);
            w[2] = make_float2(w1.x, w1.y); w[3] = make_float2(w1.z, w1.w);
            w[4] = make_float2(w2.x, w2.y); w[5] = make_float2(w2.z, w2.w);
            w[6] = make_float2(w3.x, w3.y); w[7] = make_float2(w3.z, w3.w);
#pragma unroll
            for (int m = 0; m < 4; m++) {
                float xm = xs[(ng + m) * G_XS + k];
                float2 xp = make_float2(xm, xm);
#pragma unroll
                for (int j = 0; j < 8; j++)
                    fma2(acc[m][j], xp, w[j], acc[m][j]);
            }
        }
    }

    float* base = half ? g_xr1 : g_xl1;
#pragma unroll
    for (int m = 0; m < 4; m++) {
        int node = nodeBase + ng + m;
        if (node < NN) {
            float* dstp = base + node * 16;
            *(float4*)(dstp + 0)  = make_float4(acc[m][0].x, acc[m][0].y, acc[m][1].x, acc[m][1].y);
            *(float4*)(dstp + 4)  = make_float4(acc[m][2].x, acc[m][2].y, acc[m][3].x, acc[m][3].y);
            *(float4*)(dstp + 8)  = make_float4(acc[m][4].x, acc[m][4].y, acc[m][5].x, acc[m][5].y);
            *(float4*)(dstp + 12) = make_float4(acc[m][6].x, acc[m][6].y, acc[m][7].x, acc[m][7].y);
        }
    }
}

// ---------------- K4: edge layer 1 + fused node2 — f32x2-packed loop --------
__global__ void __launch_bounds__(128, 14)
edge1_kernel(const float* __restrict__ a1,
             const float* __restrict__ b1,
             const float* __restrict__ W2l,
             const float* __restrict__ W2r) {
    __shared__ float sW[256];   // [k][16]: c<8 -> W2l col c, c>=8 -> W2r col c-8
    int t = threadIdx.x;
    {
        int k = t >> 3, c = t & 7;
        sW[k * 16 + c]     = W2l[t];
        sW[k * 16 + 8 + c] = W2r[t];
    }
    __syncthreads();

    int warp = (blockIdx.x * blockDim.x + t) >> 5;   // grid = exactly NN warps
    int lane = t & 31;
    int h = lane & 3;            // head / float4 index
    int eg = lane >> 2;          // edge slot 0..7

    int d = warp;
    int cnt = g_cnt[d];
    int len = cnt < K_SLOT ? cnt : K_SLOT;
    const int* ep = g_esrc2 + d * K_SLOT;

    float4 aa = __ldg((const float4*)a1 + h);
    float2 aa01 = make_float2(aa.x, aa.y);
    float2 aa23 = make_float2(aa.z, aa.w);
    float4 xr = *((const float4*)(g_xr1 + d * 16) + h);
    float2 xr01 = make_float2(xr.x, xr.y);
    float2 xr23 = make_float2(xr.z, xr.w);
    const float2 c02 = make_float2(0.2f, 0.2f);

    float2 acc01 = make_float2(0.f, 0.f), acc23 = make_float2(0.f, 0.f);
    float den = 0.0f;
    int lenUp = (len + 7) & ~7;
#pragma unroll 2
    for (int j = eg; j < lenUp; j += 8) {
        bool valid = j < len;
        int s = valid ? ep[j] : 0;
        float4 xl = *((const float4*)(g_xl1 + s * 16) + h);
        float2 xl01 = make_float2(xl.x, xl.y);
        float2 xl23 = make_float2(xl.z, xl.w);
        float2 v01 = add2(xl01, xr01);
        float2 v23 = add2(xl23, xr23);
        float2 t01 = mul2(v01, c02);
        float2 t23 = mul2(v23, c02);
        float2 lr01 = make_float2(fmaxf(v01.x, t01.x), fmaxf(v01.y, t01.y));
        float2 lr23 = make_float2(fmaxf(v23.x, t23.x), fmaxf(v23.y, t23.y));
        float2 lgv = make_float2(0.f, 0.f);
        fma2(lgv, aa01, lr01, lgv);
        fma2(lgv, aa23, lr23, lgv);
        float lg = lgv.x + lgv.y;
        float ex = valid ? __expf(lg) : 0.0f;
        den += ex;
        float2 exx = make_float2(ex, ex);
        fma2(acc01, exx, xl01, acc01);
        fma2(acc23, exx, xl23, acc23);
    }
    // spill fallback (empty in practice)
    if (cnt > K_SLOT) {
        int ns = g_spill_cnt; if (ns > SPILL_MAX) ns = SPILL_MAX;
        for (int q = 0; q < ns; q++) {
            if (g_spill_d[q] == d && eg == 0) {
                int s = g_spill_s[q];
                float4 xl = *((const float4*)(g_xl1 + s * 16) + h);
                float lg = aa.x * lrelu02(xl.x + xr.x)
                         + aa.y * lrelu02(xl.y + xr.y)
                         + aa.z * lrelu02(xl.z + xr.z)
                         + aa.w * lrelu02(xl.w + xr.w);
                float ex = __expf(lg);
                den += ex;
                acc01.x = fmaf(ex, xl.x, acc01.x);
                acc01.y = fmaf(ex, xl.y, acc01.y);
                acc23.x = fmaf(ex, xl.z, acc23.x);
                acc23.y = fmaf(ex, xl.w, acc23.y);
            }
        }
    }
    float4 acc = make_float4(acc01.x, acc01.y, acc23.x, acc23.y);
    // reduce across 8 edge groups
#pragma unroll
    for (int o = 4; o < 32; o <<= 1) {
        acc.x += __shfl_xor_sync(0xFFFFFFFFu, acc.x, o);
        acc.y += __shfl_xor_sync(0xFFFFFFFFu, acc.y, o);
        acc.z += __shfl_xor_sync(0xFFFFFFFFu, acc.z, o);
        acc.w += __shfl_xor_sync(0xFFFFFFFFu, acc.w, o);
        den   += __shfl_xor_sync(0xFFFFFFFFu, den, o);
    }

    // fused node2: normalize + bias + ELU (every lane has its head's result)
    float inv = 1.0f / (den + 1e-16f);
    float4 bb = __ldg((const float4*)b1 + h);
    float v4[4];
    {
        float t0 = acc.x * inv + bb.x;
        float t1 = acc.y * inv + bb.y;
        float t2 = acc.z * inv + bb.z;
        float t3 = acc.w * inv + bb.w;
        v4[0] = (t0 > 0.0f) ? t0 : (__expf(t0) - 1.0f);
        v4[1] = (t1 > 0.0f) ? t1 : (__expf(t1) - 1.0f);
        v4[2] = (t2 > 0.0f) ? t2 : (__expf(t2) - 1.0f);
        v4[3] = (t3 > 0.0f) ? t3 : (__expf(t3) - 1.0f);
    }
    // 16-wide transform: v[k] lives in lane (k>>2) (replicated mod 4), reg k&3
    int cc = lane & 15;
    float o = 0.0f;
#pragma unroll
    for (int k = 0; k < 16; k++) {
        float vk = __shfl_sync(0xFFFFFFFFu, v4[k & 3], k >> 2);
        o = fmaf(vk, sW[k * 16 + cc], o);
    }
    if (lane < 8)       g_xl2[d * 8 + lane] = o;
    else if (lane < 16) g_xr2[d * 8 + (lane - 8)] = o;
}

// ---------------- K5: edge layer 2 — f32x2-packed loop ----------------
__global__ void __launch_bounds__(128, 14)
edge2_kernel(const float* __restrict__ a2,
             const float* __restrict__ b2,
             float* __restrict__ out) {
    int warp = (blockIdx.x * blockDim.x + threadIdx.x) >> 5;
    int lane = threadIdx.x & 31;
    int hf = lane & 1;           // which float4 half of the 8 channels
    int eg = lane >> 1;          // edge slot 0..15

    int d = warp;
    int cnt = g_cnt[d];
    int len = cnt < K_SLOT ? cnt : K_SLOT;
    const int* ep = g_esrc2 + d * K_SLOT;

    float4 aa = __ldg((const float4*)a2 + hf);
    float2 aa01 = make_float2(aa.x, aa.y);
    float2 aa23 = make_float2(aa.z, aa.w);
    float4 xr = *((const float4*)(g_xr2 + d * 8) + hf);
    float2 xr01 = make_float2(xr.x, xr.y);
    float2 xr23 = make_float2(xr.z, xr.w);
    const float2 c02 = make_float2(0.2f, 0.2f);

    float2 acc01 = make_float2(0.f, 0.f), acc23 = make_float2(0.f, 0.f);
    float den = 0.0f;
    int lenUp = (len + 15) & ~15;
#pragma unroll 2
    for (int j = eg; j < lenUp; j += 16) {
        bool valid = j < len;
        int s = valid ? ep[j] : 0;
        float4 xl = *((const float4*)(g_xl2 + s * 8) + hf);
        float2 xl01 = make_float2(xl.x, xl.y);
        float2 xl23 = make_float2(xl.z, xl.w);
        float2 v01 = add2(xl01, xr01);
        float2 v23 = add2(xl23, xr23);
        float2 t01 = mul2(v01, c02);
        float2 t23 = mul2(v23, c02);
        float2 lr01 = make_float2(fmaxf(v01.x, t01.x), fmaxf(v01.y, t01.y));
        float2 lr23 = make_float2(fmaxf(v23.x, t23.x), fmaxf(v23.y, t23.y));
        float2 lgv = make_float2(0.f, 0.f);
        fma2(lgv, aa01, lr01, lgv);
        fma2(lgv, aa23, lr23, lgv);
        float tt = lgv.x + lgv.y;
        tt += __shfl_xor_sync(0xFFFFFFFFu, tt, 1);
        float ex = valid ? __expf(tt) : 0.0f;
        den += ex;
        float2 exx = make_float2(ex, ex);
        fma2(acc01, exx, xl01, acc01);
        fma2(acc23, exx, xl23, acc23);
    }
    if (cnt > K_SLOT) {
        int ns = g_spill_cnt; if (ns > SPILL_MAX) ns = SPILL_MAX;
        for (int q = 0; q < ns; q++) {
            if (g_spill_d[q] == d && eg == 0) {
                int s = g_spill_s[q];
                float4 xl = *((const float4*)(g_xl2 + s * 8) + hf);
                float tt = aa.x * lrelu02(xl.x + xr.x)
                         + aa.y * lrelu02(xl.y + xr.y)
                         + aa.z * lrelu02(xl.z + xr.z)
                         + aa.w * lrelu02(xl.w + xr.w);
                tt += __shfl_xor_sync(0x3u, tt, 1);
                float ex = __expf(tt);
                den += ex;
                acc01.x = fmaf(ex, xl.x, acc01.x);
                acc01.y = fmaf(ex, xl.y, acc01.y);
                acc23.x = fmaf(ex, xl.z, acc23.x);
                acc23.y = fmaf(ex, xl.w, acc23.y);
            }
        }
    }
    float4 acc = make_float4(acc01.x, acc01.y, acc23.x, acc23.y);
    // reduce across 16 edge groups (keep the lane pair distinct: skip xor 1)
#pragma unroll
    for (int o = 2; o < 32; o <<= 1) {
        acc.x += __shfl_xor_sync(0xFFFFFFFFu, acc.x, o);
        acc.y += __shfl_xor_sync(0xFFFFFFFFu, acc.y, o);
        acc.z += __shfl_xor_sync(0xFFFFFFFFu, acc.z, o);
        acc.w += __shfl_xor_sync(0xFFFFFFFFu, acc.w, o);
        den   += __shfl_xor_sync(0xFFFFFFFFu, den, o);
    }

    if (lane < 2) {   // lane 0: channels 0-3, lane 1: channels 4-7
        float inv = 1.0f / (den + 1e-16f);
        float4 bb = __ldg((const float4*)b2 + lane);
        float4 r;
        r.x = 1.0f / (1.0f + __expf(-(acc.x * inv + bb.x)));
        r.y = 1.0f / (1.0f + __expf(-(acc.y * inv + bb.y)));
        r.z = 1.0f / (1.0f + __expf(-(acc.z * inv + bb.z)));
        r.w = 1.0f / (1.0f + __expf(-(acc.w * inv + bb.w)));
        *((float4*)(out + d * 8) + lane) = r;
    }
}

// ---------------- launch ----------------
extern "C" void kernel_launch(void* const* d_in, const int* in_sizes, int n_in,
                              void* d_out, int out_size) {
    const float* x   = (const float*)d_in[0];
    const void*  ei  = d_in[1];
    const float* W1l = (const float*)d_in[2];
    const float* W1r = (const float*)d_in[3];
    const float* a1  = (const float*)d_in[4];
    const float* b1  = (const float*)d_in[5];
    const float* W2l = (const float*)d_in[6];
    const float* W2r = (const float*)d_in[7];
    const float* a2  = (const float*)d_in[8];
    const float* b2  = (const float*)d_in[9];
    float* out = (float*)d_out;

    static bool configured = false;
    static cudaStream_t s2;
    static cudaEvent_t evA, evB;
    if (!configured) {
        cudaFuncSetAttribute(gemm1_kernel,
                             cudaFuncAttributeMaxDynamicSharedMemorySize,
                             (int)G_SMEM);
        cudaStreamCreateWithFlags(&s2, cudaStreamNonBlocking);
        cudaEventCreateWithFlags(&evA, cudaEventDisableTiming);
        cudaEventCreateWithFlags(&evB, cudaEventDisableTiming);
        configured = true;
    }

    const int NWB = (NN * 32) / 128;   // 25000 blocks of 128 = 100000 warps

    // fork: gemm1 on s2 in parallel with bucket build on default stream
    cudaEventRecord(evA, 0);
    cudaStreamWaitEvent(s2, evA, 0);
    gemm1_kernel<<<(NN + G_NODES - 1) / G_NODES, 256, G_SMEM, s2>>>(x, W1l, W1r);
    cudaEventRecord(evB, s2);

    init_kernel<<<(NN + 1023) / 1024, 1024>>>((const long long*)ei);
    build_kernel<<<(EE / 2 + 255) / 256, 256>>>(ei);

    // join
    cudaStreamWaitEvent(0, evB, 0);
    edge1_kernel<<<NWB, 128>>>(a1, b1, W2l, W2r);
    edge2_kernel<<<NWB, 128>>>(a2, b2, out);
}

// round 16
// speedup vs baseline: 1.2848x; 1.0804x over previous
#include <cuda_runtime.h>
#include <cuda_bf16.h>

#define NN 100000
#define EE 3200000
#define K_SLOT 80
#define SPILL_MAX 65536

// ---------------- scratch (device globals; no allocations) ----------------
__device__ int   g_esrc2[NN * K_SLOT];   // bucketed src per dst (fixed stride)
__device__ int   g_cnt[NN];
__device__ int   g_spill_s[SPILL_MAX];
__device__ int   g_spill_d[SPILL_MAX];
__device__ int   g_spill_cnt;
__device__ float g_xl1[NN * 16];
__device__ float g_xr1[NN * 16];
__device__ float g_xl2[NN * 8];
__device__ float g_xr2[NN * 8];
__device__ int   g_is64;

// ---------------- helpers ----------------
__device__ __forceinline__ float lrelu02(float x) {
    return fmaxf(x, 0.2f * x);
}

__device__ __forceinline__ void fma2(float2& d, float2 a, float2 b, float2 c) {
    asm("fma.rn.f32x2 %0, %1, %2, %3;"
        : "=l"(reinterpret_cast<unsigned long long&>(d))
        : "l"(reinterpret_cast<unsigned long long&>(a)),
          "l"(reinterpret_cast<unsigned long long&>(b)),
          "l"(reinterpret_cast<unsigned long long&>(c)));
}

// ---------------- K1: zero counters + detect dtype ----------------
__global__ void init_kernel(const long long* __restrict__ ei) {
    int i = blockIdx.x * blockDim.x + threadIdx.x;
    if (i < NN) g_cnt[i] = 0;
    if (blockIdx.x == 0) {
        if (threadIdx.x == 0) g_spill_cnt = 0;
        int bad = 0;
        for (int j = threadIdx.x; j < 2048; j += 1024) {
            long long v = ei[j];
            if (v < 0 || v >= (long long)NN) bad = 1;
        }
        bad = __syncthreads_or(bad);
        if (threadIdx.x == 0) g_is64 = bad ? 0 : 1;
    }
}

// ---------------- K2: single-pass bucket build (2 edges/thread, 16B loads) --
__global__ void build_kernel(const void* __restrict__ ei) {
    int i = (blockIdx.x * blockDim.x + threadIdx.x) * 2;
    if (i >= EE) return;
    int s0, s1, d0, d1;
    if (g_is64) {
        longlong2 sv = *(const longlong2*)((const long long*)ei + i);
        longlong2 dv = *(const longlong2*)((const long long*)ei + EE + i);
        s0 = (int)sv.x; s1 = (int)sv.y;
        d0 = (int)dv.x; d1 = (int)dv.y;
    } else {
        int2 sv = *(const int2*)((const int*)ei + i);
        int2 dv = *(const int2*)((const int*)ei + EE + i);
        s0 = sv.x; s1 = sv.y;
        d0 = dv.x; d1 = dv.y;
    }
    int p0 = atomicAdd(&g_cnt[d0], 1);
    if (p0 < K_SLOT) {
        g_esrc2[d0 * K_SLOT + p0] = s0;
    } else {
        int q = atomicAdd(&g_spill_cnt, 1);
        if (q < SPILL_MAX) { g_spill_s[q] = s0; g_spill_d[q] = d0; }
    }
    int p1 = atomicAdd(&g_cnt[d1], 1);
    if (p1 < K_SLOT) {
        g_esrc2[d1 * K_SLOT + p1] = s1;
    } else {
        int q = atomicAdd(&g_spill_cnt, 1);
        if (q < SPILL_MAX) { g_spill_s[q] = s1; g_spill_d[q] = d1; }
    }
}

// ---------------- K3: GEMM1 — f32x2 packed FMA (round-9 winner) ------------
#define G_NODES 512
#define G_KC    16
#define G_XS    (G_KC + 1)
#define G_SMEM  ((256 * 32 + G_NODES * G_XS) * sizeof(float))

__global__ void __launch_bounds__(256, 2)
gemm1_kernel(const float* __restrict__ x,
             const float* __restrict__ W1l,
             const float* __restrict__ W1r) {
    extern __shared__ float smem[];
    float* Ws = smem;                 // [256 k][32 c]
    float* xs = smem + 256 * 32;      // [512 node][G_XS]

    int t = threadIdx.x;
    for (int i = t; i < 256 * 16; i += 256) {
        int k = i >> 4, c = i & 15;
        Ws[k * 32 + c]      = W1l[i];
        Ws[k * 32 + 16 + c] = W1r[i];
    }

    int nodeBase = blockIdx.x * G_NODES;
    int half = t & 1;
    int ng = (t >> 1) * 4;

    float2 acc[4][8];
#pragma unroll
    for (int m = 0; m < 4; m++)
#pragma unroll
        for (int j = 0; j < 8; j++) acc[m][j] = make_float2(0.f, 0.f);

    for (int kc = 0; kc < 256; kc += G_KC) {
        __syncthreads();
#pragma unroll
        for (int it = 0; it < 8; it++) {
            int idx = t + 256 * it;
            int node = idx >> 2;
            int k4 = (idx & 3) * 4;
            int gnode = nodeBase + node;
            float4 v = (gnode < NN)
                ? *(const float4*)(x + (size_t)gnode * 256 + kc + k4)
                : make_float4(0.f, 0.f, 0.f, 0.f);
            float* p = xs + node * G_XS + k4;
            p[0] = v.x; p[1] = v.y; p[2] = v.z; p[3] = v.w;
        }
        __syncthreads();

#pragma unroll
        for (int k = 0; k < G_KC; k++) {
            const float4* wp = (const float4*)&Ws[(kc + k) * 32 + half * 16];
            float4 w0 = wp[0], w1 = wp[1], w2 = wp[2], w3 = wp[3];
            float2 w[8];
            w[0] = make_float2(w0.x, w0.y); w[1] = make_float2(w0.z, w0.w);
            w[2] = make_float2(w1.x, w1.y); w[3] = make_float2(w1.z, w1.w);
            w[4] = make_float2(w2.x, w2.y); w[5] = make_float2(w2.z, w2.w);
            w[6] = make_float2(w3.x, w3.y); w[7] = make_float2(w3.z, w3.w);
#pragma unroll
            for (int m = 0; m < 4; m++) {
                float xm = xs[(ng + m) * G_XS + k];
                float2 xp = make_float2(xm, xm);
#pragma unroll
                for (int j = 0; j < 8; j++)
                    fma2(acc[m][j], xp, w[j], acc[m][j]);
            }
        }
    }

    float* base = half ? g_xr1 : g_xl1;
#pragma unroll
    for (int m = 0; m < 4; m++) {
        int node = nodeBase + ng + m;
        if (node < NN) {
            float* dstp = base + node * 16;
            *(float4*)(dstp + 0)  = make_float4(acc[m][0].x, acc[m][0].y, acc[m][1].x, acc[m][1].y);
            *(float4*)(dstp + 4)  = make_float4(acc[m][2].x, acc[m][2].y, acc[m][3].x, acc[m][3].y);
            *(float4*)(dstp + 8)  = make_float4(acc[m][4].x, acc[m][4].y, acc[m][5].x, acc[m][5].y);
            *(float4*)(dstp + 12) = make_float4(acc[m][6].x, acc[m][6].y, acc[m][7].x, acc[m][7].y);
        }
    }
}

// ---------------- K4: edge layer 1 + fused node2 — TWO nodes per warp ------
// 16 lanes per node; per node: 4 lanes/edge (lane=head=float4), 4 edge slots.
// Reduce: 2 shuffle rounds; node2 transform produces both nodes at once.
__global__ void __launch_bounds__(128, 14)
edge1_kernel(const float* __restrict__ a1,
             const float* __restrict__ b1,
             const float* __restrict__ W2l,
             const float* __restrict__ W2r) {
    __shared__ float sW[256];   // [k][16]: c<8 -> W2l col c, c>=8 -> W2r col c-8
    int t = threadIdx.x;
    {
        int k = t >> 3, c = t & 7;
        sW[k * 16 + c]     = W2l[t];
        sW[k * 16 + 8 + c] = W2r[t];
    }
    __syncthreads();

    int warp = (blockIdx.x * blockDim.x + t) >> 5;   // grid = NN/2 warps
    int lane = t & 31;
    int half16 = lane >> 4;      // which node of the pair
    int l = lane & 15;           // lane within node group
    int h = l & 3;               // head / float4 index
    int eg = l >> 2;             // edge slot 0..3

    int d = warp * 2 + half16;   // NN even -> always < NN
    int cnt = g_cnt[d];
    int len = cnt < K_SLOT ? cnt : K_SLOT;
    const int* ep = g_esrc2 + d * K_SLOT;

    float4 aa = __ldg((const float4*)a1 + h);
    float4 xr = *((const float4*)(g_xr1 + d * 16) + h);

    float4 acc = make_float4(0.f, 0.f, 0.f, 0.f);
    float den = 0.0f;
    int lenUp = (len + 3) & ~3;
#pragma unroll 2
    for (int j = eg; j < lenUp; j += 4) {
        bool valid = j < len;
        int s = valid ? ep[j] : 0;
        float4 xl = *((const float4*)(g_xl1 + s * 16) + h);
        float lg = aa.x * lrelu02(xl.x + xr.x)
                 + aa.y * lrelu02(xl.y + xr.y)
                 + aa.z * lrelu02(xl.z + xr.z)
                 + aa.w * lrelu02(xl.w + xr.w);
        float ex = valid ? __expf(lg) : 0.0f;
        den += ex;
        acc.x = fmaf(ex, xl.x, acc.x);
        acc.y = fmaf(ex, xl.y, acc.y);
        acc.z = fmaf(ex, xl.z, acc.z);
        acc.w = fmaf(ex, xl.w, acc.w);
    }
    // spill fallback (empty in practice) — warp-uniform control flow
    if (__any_sync(0xFFFFFFFFu, cnt > K_SLOT)) {
        int ns = g_spill_cnt; if (ns > SPILL_MAX) ns = SPILL_MAX;
        for (int q = 0; q < ns; q++) {
            bool match = (g_spill_d[q] == d) && (eg == 0);
            int s = g_spill_s[q];
            float4 xl = *((const float4*)(g_xl1 + s * 16) + h);
            float lg = aa.x * lrelu02(xl.x + xr.x)
                     + aa.y * lrelu02(xl.y + xr.y)
                     + aa.z * lrelu02(xl.z + xr.z)
                     + aa.w * lrelu02(xl.w + xr.w);
            lg += __shfl_xor_sync(0xFFFFFFFFu, lg, 1);
            lg += __shfl_xor_sync(0xFFFFFFFFu, lg, 2);
            float ex = match ? __expf(lg) : 0.0f;
            den += ex;
            acc.x = fmaf(ex, xl.x, acc.x);
            acc.y = fmaf(ex, xl.y, acc.y);
            acc.z = fmaf(ex, xl.z, acc.z);
            acc.w = fmaf(ex, xl.w, acc.w);
        }
    }
    // reduce across 4 edge groups (xor 4, 8 stays within the 16-lane half)
#pragma unroll
    for (int o = 4; o < 16; o <<= 1) {
        acc.x += __shfl_xor_sync(0xFFFFFFFFu, acc.x, o);
        acc.y += __shfl_xor_sync(0xFFFFFFFFu, acc.y, o);
        acc.z += __shfl_xor_sync(0xFFFFFFFFu, acc.z, o);
        acc.w += __shfl_xor_sync(0xFFFFFFFFu, acc.w, o);
        den   += __shfl_xor_sync(0xFFFFFFFFu, den, o);
    }

    // fused node2: normalize + bias + ELU (every lane of the half has its head)
    float inv = 1.0f / (den + 1e-16f);
    float4 bb = __ldg((const float4*)b1 + h);
    float v4[4];
    {
        float t0 = acc.x * inv + bb.x;
        float t1 = acc.y * inv + bb.y;
        float t2 = acc.z * inv + bb.z;
        float t3 = acc.w * inv + bb.w;
        v4[0] = (t0 > 0.0f) ? t0 : (__expf(t0) - 1.0f);
        v4[1] = (t1 > 0.0f) ? t1 : (__expf(t1) - 1.0f);
        v4[2] = (t2 > 0.0f) ? t2 : (__expf(t2) - 1.0f);
        v4[3] = (t3 > 0.0f) ? t3 : (__expf(t3) - 1.0f);
    }
    // 16-wide transform per half (segmented shfl, width 16): both nodes at once
    float o = 0.0f;
#pragma unroll
    for (int k = 0; k < 16; k++) {
        float vk = __shfl_sync(0xFFFFFFFFu, v4[k & 3], k >> 2, 16);
        o = fmaf(vk, sW[k * 16 + l], o);
    }
    if (l < 8) g_xl2[d * 8 + l] = o;
    else       g_xr2[d * 8 + (l - 8)] = o;
}

// ---------------- K5: edge layer 2 (round-9 winner) ----------------
__global__ void __launch_bounds__(128, 14)
edge2_kernel(const float* __restrict__ a2,
             const float* __restrict__ b2,
             float* __restrict__ out) {
    int warp = (blockIdx.x * blockDim.x + threadIdx.x) >> 5;
    int lane = threadIdx.x & 31;
    int hf = lane & 1;           // which float4 half of the 8 channels
    int eg = lane >> 1;          // edge slot 0..15

    int d = warp;
    int cnt = g_cnt[d];
    int len = cnt < K_SLOT ? cnt : K_SLOT;
    const int* ep = g_esrc2 + d * K_SLOT;

    float4 aa = __ldg((const float4*)a2 + hf);
    float4 xr = *((const float4*)(g_xr2 + d * 8) + hf);

    float4 acc = make_float4(0.f, 0.f, 0.f, 0.f);
    float den = 0.0f;
    int lenUp = (len + 15) & ~15;
#pragma unroll 2
    for (int j = eg; j < lenUp; j += 16) {
        bool valid = j < len;
        int s = valid ? ep[j] : 0;
        float4 xl = *((const float4*)(g_xl2 + s * 8) + hf);
        float t = aa.x * lrelu02(xl.x + xr.x)
                + aa.y * lrelu02(xl.y + xr.y)
                + aa.z * lrelu02(xl.z + xr.z)
                + aa.w * lrelu02(xl.w + xr.w);
        t += __shfl_xor_sync(0xFFFFFFFFu, t, 1);
        float ex = valid ? __expf(t) : 0.0f;
        den += ex;
        acc.x = fmaf(ex, xl.x, acc.x);
        acc.y = fmaf(ex, xl.y, acc.y);
        acc.z = fmaf(ex, xl.z, acc.z);
        acc.w = fmaf(ex, xl.w, acc.w);
    }
    if (cnt > K_SLOT) {
        int ns = g_spill_cnt; if (ns > SPILL_MAX) ns = SPILL_MAX;
        for (int q = 0; q < ns; q++) {
            if (g_spill_d[q] == d) {
                if (eg == 0) {
                    int s = g_spill_s[q];
                    float4 xl = *((const float4*)(g_xl2 + s * 8) + hf);
                    float t = aa.x * lrelu02(xl.x + xr.x)
                            + aa.y * lrelu02(xl.y + xr.y)
                            + aa.z * lrelu02(xl.z + xr.z)
                            + aa.w * lrelu02(xl.w + xr.w);
                    t += __shfl_xor_sync(0x3u, t, 1);
                    float ex = __expf(t);
                    den += ex;
                    acc.x = fmaf(ex, xl.x, acc.x);
                    acc.y = fmaf(ex, xl.y, acc.y);
                    acc.z = fmaf(ex, xl.z, acc.z);
                    acc.w = fmaf(ex, xl.w, acc.w);
                }
            }
        }
    }
    // reduce across 16 edge groups (keep the lane pair distinct: skip xor 1)
#pragma unroll
    for (int o = 2; o < 32; o <<= 1) {
        acc.x += __shfl_xor_sync(0xFFFFFFFFu, acc.x, o);
        acc.y += __shfl_xor_sync(0xFFFFFFFFu, acc.y, o);
        acc.z += __shfl_xor_sync(0xFFFFFFFFu, acc.z, o);
        acc.w += __shfl_xor_sync(0xFFFFFFFFu, acc.w, o);
        den   += __shfl_xor_sync(0xFFFFFFFFu, den, o);
    }

    if (lane < 2) {   // lane 0: channels 0-3, lane 1: channels 4-7
        float inv = 1.0f / (den + 1e-16f);
        float4 bb = __ldg((const float4*)b2 + lane);
        float4 r;
        r.x = 1.0f / (1.0f + __expf(-(acc.x * inv + bb.x)));
        r.y = 1.0f / (1.0f + __expf(-(acc.y * inv + bb.y)));
        r.z = 1.0f / (1.0f + __expf(-(acc.z * inv + bb.z)));
        r.w = 1.0f / (1.0f + __expf(-(acc.w * inv + bb.w)));
        *((float4*)(out + d * 8) + lane) = r;
    }
}

// ---------------- launch ----------------
extern "C" void kernel_launch(void* const* d_in, const int* in_sizes, int n_in,
                              void* d_out, int out_size) {
    const float* x   = (const float*)d_in[0];
    const void*  ei  = d_in[1];
    const float* W1l = (const float*)d_in[2];
    const float* W1r = (const float*)d_in[3];
    const float* a1  = (const float*)d_in[4];
    const float* b1  = (const float*)d_in[5];
    const float* W2l = (const float*)d_in[6];
    const float* W2r = (const float*)d_in[7];
    const float* a2  = (const float*)d_in[8];
    const float* b2  = (const float*)d_in[9];
    float* out = (float*)d_out;

    static bool configured = false;
    static cudaStream_t s2;
    static cudaEvent_t evA, evB;
    if (!configured) {
        cudaFuncSetAttribute(gemm1_kernel,
                             cudaFuncAttributeMaxDynamicSharedMemorySize,
                             (int)G_SMEM);
        cudaStreamCreateWithFlags(&s2, cudaStreamNonBlocking);
        cudaEventCreateWithFlags(&evA, cudaEventDisableTiming);
        cudaEventCreateWithFlags(&evB, cudaEventDisableTiming);
        configured = true;
    }

    const int NWB1 = (NN / 2 * 32) / 128;  // 12500 blocks: 2 nodes per warp
    const int NWB2 = (NN * 32) / 128;      // 25000 blocks: 1 node per warp

    // fork: gemm1 on s2 in parallel with bucket build on default stream
    cudaEventRecord(evA, 0);
    cudaStreamWaitEvent(s2, evA, 0);
    gemm1_kernel<<<(NN + G_NODES - 1) / G_NODES, 256, G_SMEM, s2>>>(x, W1l, W1r);
    cudaEventRecord(evB, s2);

    init_kernel<<<(NN + 1023) / 1024, 1024>>>((const long long*)ei);
    build_kernel<<<(EE / 2 + 255) / 256, 256>>>(ei);

    // join
    cudaStreamWaitEvent(0, evB, 0);
    edge1_kernel<<<NWB1, 128>>>(a1, b1, W2l, W2r);
    edge2_kernel<<<NWB2, 128>>>(a2, b2, out);
}